// round 2
// baseline (speedup 1.0000x reference)
#include <cuda_runtime.h>
#include <math.h>
#include <stdint.h>

// Problem constants (fixed shapes from the reference setup)
#define BQ    4
#define NP    16384
#define SQ    2048
#define KNN   32
#define NQTOT (BQ*SQ)          // 8192 query points
#define MROWS (NQTOT*KNN)      // 262144 grouped rows
#define RAD2  0.04f
#define BN_EPS 1e-5f

// ---------------- scratch (device globals; no allocations allowed) ----------
__device__ int   g_idx[MROWS];
__device__ float g_h1[(size_t)MROWS*64];
__device__ float g_h2[(size_t)MROWS*64];
__device__ float g_h3[(size_t)MROWS*128];
__device__ float g_sum[3*128];
__device__ float g_sq[3*128];
__device__ float g_scale[3*128];
__device__ float g_shift[3*128];

// ---------------- stats reset (graph replays re-run this) -------------------
__global__ void zero_stats_kernel() {
    int t = threadIdx.x + blockIdx.x * blockDim.x;
    if (t < 3*128) { g_sum[t] = 0.f; g_sq[t] = 0.f; }
}

// ---------------- ball query: warp per query, early exit --------------------
// Rounding pattern replicates the reference lowering exactly:
//   qq, xx  : plain mul + add, no FMA contraction  ((x*x + y*y) + z*z)
//   dot     : FMA chain ascending k (GEMM-library style), first term = plain mul
//   d2      : (qq + xx) - (2*dot)   [2*dot exact; final op single rounding]
__global__ void ballquery_kernel(const float* __restrict__ xyz,
                                 const float* __restrict__ newxyz) {
    int warp = (blockIdx.x * blockDim.x + threadIdx.x) >> 5;
    int lane = threadIdx.x & 31;
    if (warp >= NQTOT) return;
    int b = warp / SQ;
    const float* q = newxyz + (size_t)warp * 3;
    float qx = q[0], qy = q[1], qz = q[2];
    float qq = __fadd_rn(__fadd_rn(__fmul_rn(qx,qx), __fmul_rn(qy,qy)),
                         __fmul_rn(qz,qz));
    const float* xb = xyz + (size_t)b * NP * 3;
    int* outp = g_idx + (size_t)warp * KNN;
    int cnt = 0;
    int first = -1;
    for (int base = 0; base < NP; base += 32) {
        int p = base + lane;
        float x = xb[p*3+0], y = xb[p*3+1], z = xb[p*3+2];
        float xx = __fadd_rn(__fadd_rn(__fmul_rn(x,x), __fmul_rn(y,y)),
                             __fmul_rn(z,z));
        float dt = fmaf(qz, z, fmaf(qy, y, __fmul_rn(qx, x)));
        float d2 = __fsub_rn(__fadd_rn(qq, xx), __fmul_rn(2.0f, dt));
        bool hit = !(d2 > RAD2);
        unsigned mask = __ballot_sync(0xffffffffu, hit);
        if (mask) {
            if (first < 0) first = base + __ffs(mask) - 1;
            int pos = cnt + __popc(mask & ((1u << lane) - 1u));
            if (hit && pos < KNN) outp[pos] = p;
            cnt += __popc(mask);
            if (cnt >= KNN) break;
        }
    }
    if (cnt < KNN) {
        if (first < 0) first = 0;
        for (int pos = cnt + lane; pos < KNN; pos += 32) outp[pos] = first;
    }
}

// ---------------- shared GEMM epilogue: bias + store + BN-stat reduce -------
template<int COUT, int TC>
__device__ __forceinline__ void gemm_epilogue(
    float (*acc)[TC], int m0, int g, int hc, int t,
    const float* __restrict__ bias,
    float* __restrict__ Y,
    float* s_sum, float* s_sq,
    float* __restrict__ gsum, float* __restrict__ gsq)
{
    float colSum[TC], colSq[TC], bv[TC];
    #pragma unroll
    for (int j = 0; j < TC; j++) { colSum[j] = 0.f; colSq[j] = 0.f; bv[j] = bias[hc*TC + j]; }
    #pragma unroll
    for (int i = 0; i < 4; i++) {
        float vals[TC];
        #pragma unroll
        for (int j = 0; j < TC; j++) {
            float yv = acc[i][j] + bv[j];
            vals[j] = yv;
            colSum[j] += yv;
            colSq[j] = fmaf(yv, yv, colSq[j]);
        }
        float* dst = Y + (size_t)(m0 + 4*g + i) * COUT + hc*TC;
        #pragma unroll
        for (int j = 0; j < TC; j += 4)
            *reinterpret_cast<float4*>(dst + j) =
                make_float4(vals[j], vals[j+1], vals[j+2], vals[j+3]);
    }
    #pragma unroll
    for (int j = 0; j < TC; j++) {
        atomicAdd(&s_sum[hc*TC + j], colSum[j]);
        atomicAdd(&s_sq[hc*TC + j],  colSq[j]);
    }
    __syncthreads();
    if (t < COUT) {
        atomicAdd(&gsum[t], s_sum[t]);
        atomicAdd(&gsq[t],  s_sq[t]);
    }
}

// ---------------- layer 1: gather (ballquery idx) + GEMM 67->64 -------------
__global__ void gemm1_kernel(const float* __restrict__ xyz,
                             const float* __restrict__ points,
                             const float* __restrict__ newxyz,
                             const float* __restrict__ W,     // [64][67]
                             const float* __restrict__ bias,
                             float* __restrict__ Y,
                             float* __restrict__ gsum,
                             float* __restrict__ gsq)
{
    extern __shared__ float sm[];
    float* Xs    = sm;                  // [67][64]
    float* Ws    = sm + 67*64;          // [67][64]
    float* s_sum = Ws + 67*64;          // [64]
    float* s_sq  = s_sum + 64;          // [64]
    const int t  = threadIdx.x;
    const int m0 = blockIdx.x * 64;

    for (int i = t; i < 64*67; i += 256) {
        int o = i / 67, c = i - o*67;
        Ws[c*64 + o] = W[i];
    }
    if (t < 64) { s_sum[t] = 0.f; s_sq[t] = 0.f; }

    {   // gather: 4 threads per row; row r = grouped point m0+r
        const int r = t >> 2, tt = t & 3;
        const int m = m0 + r;
        const int b = m >> 16;                 // / (SQ*KNN) = 65536
        const int s = (m >> 5) & (SQ - 1);     // / KNN mod SQ
        const int j = g_idx[m];
        const float4* prow =
            reinterpret_cast<const float4*>(points + (size_t)(b*NP + j) * 64) + tt*4;
        #pragma unroll
        for (int v = 0; v < 4; v++) {
            float4 x = prow[v];
            int c = 3 + tt*16 + v*4;
            Xs[(c+0)*64 + r] = x.x;
            Xs[(c+1)*64 + r] = x.y;
            Xs[(c+2)*64 + r] = x.z;
            Xs[(c+3)*64 + r] = x.w;
        }
        if (tt == 0) {
            const float* pj = xyz    + (size_t)(b*NP + j) * 3;
            const float* qv = newxyz + (size_t)(b*SQ + s) * 3;
            Xs[0*64 + r] = pj[0] - qv[0];
            Xs[1*64 + r] = pj[1] - qv[1];
            Xs[2*64 + r] = pj[2] - qv[2];
        }
    }
    __syncthreads();

    const int g = t & 15, hc = t >> 4;
    float acc[4][4];
    #pragma unroll
    for (int i = 0; i < 4; i++)
        #pragma unroll
        for (int j = 0; j < 4; j++) acc[i][j] = 0.f;

    for (int c = 0; c < 67; c++) {
        float4 xv = *reinterpret_cast<const float4*>(&Xs[c*64 + 4*g]);
        float4 wv = *reinterpret_cast<const float4*>(&Ws[c*64 + 4*hc]);
        float xr[4] = {xv.x, xv.y, xv.z, xv.w};
        float wr[4] = {wv.x, wv.y, wv.z, wv.w};
        #pragma unroll
        for (int i = 0; i < 4; i++)
            #pragma unroll
            for (int j = 0; j < 4; j++)
                acc[i][j] = fmaf(xr[i], wr[j], acc[i][j]);
    }
    gemm_epilogue<64,4>(acc, m0, g, hc, t, bias, Y, s_sum, s_sq, gsum, gsq);
}

// ---------------- layers 2/3: BN+ReLU(prev) folded into load, then GEMM -----
template<int CIN, int COUT>
__global__ void gemm_bn_kernel(const float* __restrict__ Xpre,
                               const float* __restrict__ W,     // [COUT][CIN]
                               const float* __restrict__ bias,
                               const float* __restrict__ scl,
                               const float* __restrict__ shf,
                               float* __restrict__ Y,
                               float* __restrict__ gsum,
                               float* __restrict__ gsq)
{
    extern __shared__ float sm[];
    float* Xs    = sm;                  // [CIN][64]
    float* Ws    = sm + CIN*64;         // [CIN][COUT]
    float* s_sum = Ws + CIN*COUT;
    float* s_sq  = s_sum + COUT;
    const int t  = threadIdx.x;
    const int m0 = blockIdx.x * 64;

    for (int i = t; i < CIN*COUT; i += 256) {
        int o = i / CIN, c = i - o*CIN;
        Ws[c*COUT + o] = W[i];
    }
    if (t < COUT) { s_sum[t] = 0.f; s_sq[t] = 0.f; }

    {
        const int r = t >> 2, tt = t & 3;
        const float4* src =
            reinterpret_cast<const float4*>(Xpre + (size_t)(m0 + r) * CIN) + tt*(CIN/16);
        #pragma unroll
        for (int v = 0; v < CIN/16; v++) {
            float4 x = src[v];
            int c = tt*(CIN/4) + v*4;
            Xs[(c+0)*64 + r] = fmaxf(fmaf(x.x, scl[c+0], shf[c+0]), 0.f);
            Xs[(c+1)*64 + r] = fmaxf(fmaf(x.y, scl[c+1], shf[c+1]), 0.f);
            Xs[(c+2)*64 + r] = fmaxf(fmaf(x.z, scl[c+2], shf[c+2]), 0.f);
            Xs[(c+3)*64 + r] = fmaxf(fmaf(x.w, scl[c+3], shf[c+3]), 0.f);
        }
    }
    __syncthreads();

    constexpr int TC = COUT/16;
    const int g = t & 15, hc = t >> 4;
    float acc[4][TC];
    #pragma unroll
    for (int i = 0; i < 4; i++)
        #pragma unroll
        for (int j = 0; j < TC; j++) acc[i][j] = 0.f;

    for (int c = 0; c < CIN; c++) {
        float4 xv = *reinterpret_cast<const float4*>(&Xs[c*64 + 4*g]);
        float xr[4] = {xv.x, xv.y, xv.z, xv.w};
        float wr[TC];
        #pragma unroll
        for (int j = 0; j < TC; j += 4) {
            float4 wv = *reinterpret_cast<const float4*>(&Ws[c*COUT + hc*TC + j]);
            wr[j+0] = wv.x; wr[j+1] = wv.y; wr[j+2] = wv.z; wr[j+3] = wv.w;
        }
        #pragma unroll
        for (int i = 0; i < 4; i++)
            #pragma unroll
            for (int j = 0; j < TC; j++)
                acc[i][j] = fmaf(xr[i], wr[j], acc[i][j]);
    }
    gemm_epilogue<COUT,TC>(acc, m0, g, hc, t, bias, Y, s_sum, s_sq, gsum, gsq);
}

// ---------------- BN finalize: scale/shift per channel ----------------------
__global__ void finalize_kernel(const float* __restrict__ gamma,
                                const float* __restrict__ beta,
                                int layer, int cout)
{
    int c = threadIdx.x;
    if (c < cout) {
        const float invM = 1.0f / (float)MROWS;
        float mean = g_sum[layer*128 + c] * invM;
        float var  = g_sq[layer*128 + c] * invM - mean*mean;
        float rs = rsqrtf(var + BN_EPS);
        float sc = gamma[c] * rs;
        g_scale[layer*128 + c] = sc;
        g_shift[layer*128 + c] = beta[c] - mean*sc;
    }
}

// ---------------- BN3 + ReLU + max over K + transpose -----------------------
__global__ void maxpool_kernel(float* __restrict__ out)
{
    const int q = blockIdx.x;      // b*SQ + s
    const int o = threadIdx.x;     // channel 0..127
    const int b = q / SQ, s = q - b*SQ;
    const float sc = g_scale[2*128 + o];
    const float sh = g_shift[2*128 + o];
    const float* h = g_h3 + (size_t)q * KNN * 128 + o;
    float mx = -3.402823466e38f;
    #pragma unroll
    for (int k = 0; k < KNN; k++)
        mx = fmaxf(mx, fmaf(h[(size_t)k*128], sc, sh));
    out[(size_t)(b*128 + o) * SQ + s] = fmaxf(mx, 0.f);
}

// ---------------- launch ------------------------------------------------
extern "C" void kernel_launch(void* const* d_in, const int* in_sizes, int n_in,
                              void* d_out, int out_size) {
    const float* xyz    = (const float*)d_in[0];
    const float* points = (const float*)d_in[1];
    const float* newxyz = (const float*)d_in[2];
    const float* W1 = (const float*)d_in[3],  *b1 = (const float*)d_in[4];
    const float* ga1 = (const float*)d_in[5], *be1 = (const float*)d_in[6];
    const float* W2 = (const float*)d_in[7],  *b2 = (const float*)d_in[8];
    const float* ga2 = (const float*)d_in[9], *be2 = (const float*)d_in[10];
    const float* W3 = (const float*)d_in[11], *b3 = (const float*)d_in[12];
    const float* ga3 = (const float*)d_in[13], *be3 = (const float*)d_in[14];

    float* out = (float*)d_out;
    float* outPts = out;
    // Output is (new_xyz, new_points) flattened; handle points-only too.
    if (out_size == BQ*SQ*3 + BQ*128*SQ) {
        cudaMemcpyAsync(out, newxyz, sizeof(float)*BQ*SQ*3, cudaMemcpyDeviceToDevice);
        outPts = out + BQ*SQ*3;
    }

    float *h1, *h2, *h3, *gsum, *gsq, *gscale, *gshift;
    cudaGetSymbolAddress((void**)&h1, g_h1);
    cudaGetSymbolAddress((void**)&h2, g_h2);
    cudaGetSymbolAddress((void**)&h3, g_h3);
    cudaGetSymbolAddress((void**)&gsum, g_sum);
    cudaGetSymbolAddress((void**)&gsq, g_sq);
    cudaGetSymbolAddress((void**)&gscale, g_scale);
    cudaGetSymbolAddress((void**)&gshift, g_shift);

    const int smem1 = (67*64*2 + 128) * 4;            // ~34.8 KB
    const int smem2 = (64*64*2 + 128) * 4;            // ~32.5 KB
    const int smem3 = (64*64 + 64*128 + 256) * 4;     // ~50.2 KB (> 48K default)
    cudaFuncSetAttribute(gemm1_kernel, cudaFuncAttributeMaxDynamicSharedMemorySize, smem1);
    cudaFuncSetAttribute(gemm_bn_kernel<64,64>, cudaFuncAttributeMaxDynamicSharedMemorySize, smem2);
    cudaFuncSetAttribute(gemm_bn_kernel<64,128>, cudaFuncAttributeMaxDynamicSharedMemorySize, smem3);

    zero_stats_kernel<<<1, 512>>>();
    ballquery_kernel<<<NQTOT/8, 256>>>(xyz, newxyz);

    gemm1_kernel<<<MROWS/64, 256, smem1>>>(xyz, points, newxyz, W1, b1,
                                           h1, gsum + 0, gsq + 0);
    finalize_kernel<<<1, 128>>>(ga1, be1, 0, 64);

    gemm_bn_kernel<64,64><<<MROWS/64, 256, smem2>>>(h1, W2, b2,
                                                    gscale + 0, gshift + 0,
                                                    h2, gsum + 128, gsq + 128);
    finalize_kernel<<<1, 128>>>(ga2, be2, 1, 64);

    gemm_bn_kernel<64,128><<<MROWS/64, 256, smem3>>>(h2, W3, b3,
                                                     gscale + 128, gshift + 128,
                                                     h3, gsum + 256, gsq + 256);
    finalize_kernel<<<1, 128>>>(ga3, be3, 2, 128);

    maxpool_kernel<<<NQTOT, 128>>>(outPts);
}